// round 7
// baseline (speedup 1.0000x reference)
#include <cuda_runtime.h>
#include <cuda_bf16.h>
#include <cstdint>

// ---------------------------------------------------------------- constants
#define M_ROWS 224      // B*N
#define K_DIM  49152
#define PRED   336
#define NCOLS  1344

#define SPLITS    21
#define BM        128
#define BN        96
#define NT        14    // 1344/96
#define KT        32    // k per stage
#define THREADS   256   // 8 warps: 4 (m) x 2 (n), warp tile 32x48

// smem stage layout (bytes), padded strides for conflict-free ldmatrix
#define A_STRIDE 80     // 32 bf16 = 64B + 16 pad
#define B_STRIDE 208    // 96 bf16 = 192B + 16 pad
#define AH_OFF   0
#define AL_OFF   10240  // 128*80
#define BH_OFF   20480
#define BL_OFF   27136  // +32*208
#define STAGE    33792
#define NSTAGES  3
#define SMEM_NEED (NSTAGES * STAGE)   // 101376 -> 2 CTAs/SM

// scratch
__device__ float g_part[SPLITS * M_ROWS * NCOLS];
__device__ __nv_bfloat16 g_XH[(size_t)M_ROWS * K_DIM];
__device__ __nv_bfloat16 g_XL[(size_t)M_ROWS * K_DIM];

// db4 reconstruction filters
__constant__ float c_RL[8] = {
     0.23037781330885523f,  0.7148465705525415f,   0.6308807679295904f,
    -0.02798376941698385f, -0.18703481171888114f,  0.030841381835986965f,
     0.032883011666982945f, -0.010597401784997278f };
__constant__ float c_RH[8] = {
     0.010597401784997278f, 0.032883011666982945f, -0.030841381835986965f,
    -0.18703481171888114f,  0.02798376941698385f,   0.6308807679295904f,
    -0.7148465705525415f,   0.23037781330885523f };

// ---------------------------------------------------------------- helpers
__device__ __forceinline__ uint32_t smem_u32(const void* p) {
    uint32_t a;
    asm("{ .reg .u64 t; cvta.to.shared.u64 t, %1; cvt.u32.u64 %0, t; }"
        : "=r"(a) : "l"(p));
    return a;
}

#define CP_ASYNC16(saddr, gptr)                                               \
    asm volatile("cp.async.cg.shared.global [%0], [%1], 16;"                  \
        :: "r"(saddr), "l"(gptr))
#define CP_COMMIT() asm volatile("cp.async.commit_group;" ::: "memory")
#define CP_WAIT1()  asm volatile("cp.async.wait_group 1;" ::: "memory")

#define LDSM_X4(r0, r1, r2, r3, addr)                                         \
    asm volatile("ldmatrix.sync.aligned.m8n8.x4.shared.b16 {%0,%1,%2,%3},[%4];" \
        : "=r"(r0), "=r"(r1), "=r"(r2), "=r"(r3) : "r"(addr))

#define LDSM_X4T(r0, r1, r2, r3, addr)                                        \
    asm volatile("ldmatrix.sync.aligned.m8n8.x4.trans.shared.b16 {%0,%1,%2,%3},[%4];" \
        : "=r"(r0), "=r"(r1), "=r"(r2), "=r"(r3) : "r"(addr))

#define MMA_BF16(C, A0, A1, A2, A3, B0, B1)                                   \
  asm volatile(                                                               \
      "mma.sync.aligned.m16n8k16.row.col.f32.bf16.bf16.f32 "                  \
      "{%0,%1,%2,%3}, {%4,%5,%6,%7}, {%8,%9}, {%0,%1,%2,%3};\n"               \
      : "+f"(C[0]), "+f"(C[1]), "+f"(C[2]), "+f"(C[3])                        \
      : "r"(A0), "r"(A1), "r"(A2), "r"(A3), "r"(B0), "r"(B1))

__device__ __forceinline__ void split2(float a, float b, uint32_t& H, uint32_t& L) {
    __nv_bfloat16 ha = __float2bfloat16(a), hb = __float2bfloat16(b);
    __nv_bfloat16 la = __float2bfloat16(a - __bfloat162float(ha));
    __nv_bfloat16 lb = __float2bfloat16(b - __bfloat162float(hb));
    __nv_bfloat162 ph; ph.x = ha; ph.y = hb;
    __nv_bfloat162 pl; pl.x = la; pl.y = lb;
    H = *reinterpret_cast<uint32_t*>(&ph);
    L = *reinterpret_cast<uint32_t*>(&pl);
}

// ---------------------------------------------------------------------------
// Pre-pass: X fp32 -> XH/XL bf16 (once)
// ---------------------------------------------------------------------------
__global__ void __launch_bounds__(256) split_x(const float* __restrict__ X)
{
    const size_t i = ((size_t)blockIdx.x * 256 + threadIdx.x) * 4;
    const float4 v = *reinterpret_cast<const float4*>(X + i);
    uint32_t h0, h1, l0, l1;
    split2(v.x, v.y, h0, l0);
    split2(v.z, v.w, h1, l1);
    *reinterpret_cast<uint2*>(g_XH + i) = make_uint2(h0, h1);
    *reinterpret_cast<uint2*>(g_XL + i) = make_uint2(l0, l1);
}

// ---------------------------------------------------------------------------
// GEMM: C[224,1344] = X @ Wcat  (split-K partials into g_part)
// BM=128 tiles, 2 CTAs/SM, 3-stage cp.async pipeline for A, B LDG+split.
// ---------------------------------------------------------------------------
__global__ void __launch_bounds__(THREADS, 2)
gemm_mma(const float* __restrict__ W)
{
    extern __shared__ char smem[];
    const uint32_t sb = smem_u32(smem);
    const int t    = threadIdx.x;
    const int lane = t & 31;
    const int warp = t >> 5;
    const int mt   = blockIdx.x & 1;          // m-tiles adjacent -> L2 reuse of W
    const int m0   = mt * BM;
    const int n0   = (blockIdx.x >> 1) * BN;
    const int split = blockIdx.y;
    // 1536 k32-tiles over 21 splits: first 3 get 74, rest 73
    const int start = split * 73 + (split < 3 ? split : 3);
    const int count = 73 + (split < 3 ? 1 : 0);

    // ---- A producer: 1024 16B-chunks (128 rows x 4 kc x 2 mats), 4/thread
    const __nv_bfloat16* agp[4];
    uint32_t asoff[4];
    #pragma unroll
    for (int i = 0; i < 4; ++i) {
        int c = t + i * THREADS;            // 0..1023
        int mat = c >> 9;                   // /512
        int rem = c & 511;
        int row = rem >> 2;
        int kc  = rem & 3;
        int grow = m0 + row; if (grow > 223) grow = 223;   // clamp (masked later)
        const __nv_bfloat16* base = mat ? g_XL : g_XH;
        agp[i] = base + (size_t)grow * K_DIM + (size_t)start * KT + kc * 8;
        asoff[i] = (mat ? AL_OFF : AH_OFF) + row * A_STRIDE + kc * 16;
    }

    // ---- B producer: 768 4-col chunks (32 k x 24), 3/thread (exact)
    const float* bgp[3];
    uint32_t bsoff[3];
    #pragma unroll
    for (int i = 0; i < 3; ++i) {
        int c = t + i * THREADS;
        int krow = c / 24, nc = c - krow * 24;
        int nB = n0 + nc * 4;
        int band = nB / PRED, p = nB - band * PRED;
        bgp[i] = W + (size_t)band * K_DIM * PRED +
                 ((size_t)start * KT + krow) * PRED + p;
        bsoff[i] = krow * B_STRIDE + nc * 8;
    }

    // ---- consumer: warp tile 32(m) x 48(n); warps 4m x 2n ----
    const int mw = warp >> 1, nw = warp & 1;
    const int mbase = mw * 32, nbase = nw * 48;
    const int li = lane & 7, lj = lane >> 3;
    int arel[2], brel[3];
    #pragma unroll
    for (int mf = 0; mf < 2; ++mf)
        arel[mf] = (mbase + mf * 16 + (lj & 1) * 8 + li) * A_STRIDE + ((lj & 2) ? 16 : 0);
    #pragma unroll
    for (int nf = 0; nf < 3; ++nf)
        brel[nf] = (li + (lj & 1) * 8) * B_STRIDE + (nbase + nf * 16 + ((lj & 2) ? 8 : 0)) * 2;

    float acc[2][6][4];
    #pragma unroll
    for (int m = 0; m < 2; ++m)
        #pragma unroll
        for (int n = 0; n < 6; ++n)
            #pragma unroll
            for (int q = 0; q < 4; ++q) acc[m][n][q] = 0.f;

    // ---- prologue: A stages 0,1 via cp.async; B stages 0,1 via LDG+STS ----
    {
        #pragma unroll
        for (int i = 0; i < 4; ++i) CP_ASYNC16(sb + asoff[i], agp[i]);
        CP_COMMIT();
        #pragma unroll
        for (int i = 0; i < 4; ++i) CP_ASYNC16(sb + STAGE + asoff[i], agp[i] + KT);
        CP_COMMIT();

        float4 f0[3], f1[3];
        #pragma unroll
        for (int i = 0; i < 3; ++i) {
            f0[i] = *reinterpret_cast<const float4*>(bgp[i]);
            f1[i] = *reinterpret_cast<const float4*>(bgp[i] + (size_t)KT * PRED);
        }
        #pragma unroll
        for (int i = 0; i < 3; ++i) {
            uint32_t h0, h1, l0, l1;
            split2(f0[i].x, f0[i].y, h0, l0);
            split2(f0[i].z, f0[i].w, h1, l1);
            *reinterpret_cast<uint2*>(smem + BH_OFF + bsoff[i]) = make_uint2(h0, h1);
            *reinterpret_cast<uint2*>(smem + BL_OFF + bsoff[i]) = make_uint2(l0, l1);
            split2(f1[i].x, f1[i].y, h0, l0);
            split2(f1[i].z, f1[i].w, h1, l1);
            *reinterpret_cast<uint2*>(smem + STAGE + BH_OFF + bsoff[i]) = make_uint2(h0, h1);
            *reinterpret_cast<uint2*>(smem + STAGE + BL_OFF + bsoff[i]) = make_uint2(l0, l1);
        }
        CP_WAIT1();          // stage 0 A complete
        __syncthreads();
    }

    // ---- main loop (3-stage rotation) ----
    int ss = 0;
    for (int it = 0; it < count; ++it) {
        const uint32_t ab = sb + ss * STAGE;
        const int wr = (it + 2 >= NSTAGES * ((it + 2) / NSTAGES)) ? (it + 2) % NSTAGES : 0;
        const bool more2 = (it + 2 < count);

        // issue A for stage it+2; prefetch B regs for it+2
        float4 fb[3];
        if (more2) {
            const uint32_t nsb = sb + wr * STAGE;
            const size_t ao = (size_t)(it + 2) * KT;
            #pragma unroll
            for (int i = 0; i < 4; ++i) CP_ASYNC16(nsb + asoff[i], agp[i] + ao);
            const size_t bo = (size_t)(it + 2) * KT * PRED;
            #pragma unroll
            for (int i = 0; i < 3; ++i)
                fb[i] = *reinterpret_cast<const float4*>(bgp[i] + bo);
        }
        if (more2) CP_COMMIT();

        // compute on stage ss: 2 x k16
        #pragma unroll
        for (int k16 = 0; k16 < KT; k16 += 16) {
            uint32_t ah[2][4], al[2][4];
            #pragma unroll
            for (int mf = 0; mf < 2; ++mf) {
                LDSM_X4(ah[mf][0], ah[mf][1], ah[mf][2], ah[mf][3],
                        ab + AH_OFF + arel[mf] + k16 * 2);
                LDSM_X4(al[mf][0], al[mf][1], al[mf][2], al[mf][3],
                        ab + AL_OFF + arel[mf] + k16 * 2);
            }
            #pragma unroll
            for (int nf = 0; nf < 3; ++nf) {
                uint32_t bh0, bh1, bh2, bh3, bl0, bl1, bl2, bl3;
                LDSM_X4T(bh0, bh1, bh2, bh3, ab + BH_OFF + brel[nf] + k16 * B_STRIDE);
                LDSM_X4T(bl0, bl1, bl2, bl3, ab + BL_OFF + brel[nf] + k16 * B_STRIDE);
                #pragma unroll
                for (int mf = 0; mf < 2; ++mf) {
                    MMA_BF16(acc[mf][2*nf],   ah[mf][0], ah[mf][1], ah[mf][2], ah[mf][3], bh0, bh1);
                    MMA_BF16(acc[mf][2*nf],   ah[mf][0], ah[mf][1], ah[mf][2], ah[mf][3], bl0, bl1);
                    MMA_BF16(acc[mf][2*nf],   al[mf][0], al[mf][1], al[mf][2], al[mf][3], bh0, bh1);
                    MMA_BF16(acc[mf][2*nf+1], ah[mf][0], ah[mf][1], ah[mf][2], ah[mf][3], bh2, bh3);
                    MMA_BF16(acc[mf][2*nf+1], ah[mf][0], ah[mf][1], ah[mf][2], ah[mf][3], bl2, bl3);
                    MMA_BF16(acc[mf][2*nf+1], al[mf][0], al[mf][1], al[mf][2], al[mf][3], bh2, bh3);
                }
            }
        }

        // convert + store B(it+2) into stage wr (freed by the it-1 barrier)
        if (more2) {
            char* nst = smem + wr * STAGE;
            #pragma unroll
            for (int i = 0; i < 3; ++i) {
                uint32_t h0, h1, l0, l1;
                split2(fb[i].x, fb[i].y, h0, l0);
                split2(fb[i].z, fb[i].w, h1, l1);
                *reinterpret_cast<uint2*>(nst + BH_OFF + bsoff[i]) = make_uint2(h0, h1);
                *reinterpret_cast<uint2*>(nst + BL_OFF + bsoff[i]) = make_uint2(l0, l1);
            }
        }
        CP_WAIT1();          // A(it+1) complete
        __syncthreads();

        ss = ss + 1; if (ss == NSTAGES) ss = 0;
    }

    // ---- epilogue: split-K partials ----
    float* gp = g_part + (size_t)split * M_ROWS * NCOLS;
    const int rr = lane >> 2, cc = (lane & 3) * 2;
    #pragma unroll
    for (int mf = 0; mf < 2; ++mf) {
        const int row = m0 + mbase + mf * 16 + rr;
        #pragma unroll
        for (int ns = 0; ns < 6; ++ns) {
            const int col = n0 + nbase + ns * 8 + cc;
            if (row < M_ROWS)
                *reinterpret_cast<float2*>(gp + (size_t)row * NCOLS + col) =
                    make_float2(acc[mf][ns][0], acc[mf][ns][1]);
            if (row + 8 < M_ROWS)
                *reinterpret_cast<float2*>(gp + (size_t)(row + 8) * NCOLS + col) =
                    make_float2(acc[mf][ns][2], acc[mf][ns][3]);
        }
    }
}

// ---------------------------------------------------------------------------
// Split-K reduce + bias + 3-level inverse SWT (db4, periodization)
// ---------------------------------------------------------------------------
__global__ void reduce_iswt(const float* __restrict__ bias, float* __restrict__ out)
{
    __shared__ float sc[4][PRED];
    const int t   = threadIdx.x;
    const int row = blockIdx.x;

    if (t < PRED) {
        #pragma unroll
        for (int band = 0; band < 4; ++band) {
            float a = bias[band * PRED + t];
            const float* gp = g_part + (size_t)row * NCOLS + band * PRED + t;
            #pragma unroll
            for (int s = 0; s < SPLITS; ++s)
                a += gp[(size_t)s * M_ROWS * NCOLS];
            sc[band][t] = a;
        }
    }
    __syncthreads();

    const int steps[3] = {4, 2, 1};
    #pragma unroll
    for (int lv = 0; lv < 3; ++lv) {
        const int step = steps[lv];
        const int band = lv + 1;
        const int Mlen = PRED / step;
        float nv = 0.f;
        if (t < PRED) {
            const int s = t % step;
            const int m = t / step;
            float x1 = 0.f, x2 = 0.f;
            #pragma unroll
            for (int k = 0; k < 8; ++k) {
                int q = m + 3 - k;
                if (q >= Mlen) q -= Mlen;
                if (q < 0)     q += Mlen;
                if ((q & 1) == 0) {
                    const int idx = q * step + s;
                    x1 += sc[0][idx] * c_RL[k] + sc[band][idx] * c_RH[k];
                }
                int q2 = m + 2 - k;
                if (q2 >= Mlen) q2 -= Mlen;
                if (q2 < 0)     q2 += Mlen;
                if ((q2 & 1) == 0) {
                    const int idx2 = (q2 + 1) * step + s;
                    x2 += sc[0][idx2] * c_RL[k] + sc[band][idx2] * c_RH[k];
                }
            }
            nv = 0.5f * (x1 + x2);
        }
        __syncthreads();
        if (t < PRED) sc[0][t] = nv;
        __syncthreads();
    }

    if (t < PRED) out[(size_t)row * PRED + t] = sc[0][t];
}

// ---------------------------------------------------------------------------
extern "C" void kernel_launch(void* const* d_in, const int* in_sizes, int n_in,
                              void* d_out, int out_size)
{
    const float* X    = (const float*)d_in[0];  // (224, 49152)
    const float* W    = (const float*)d_in[1];  // (4, 49152, 336)
    const float* bias = (const float*)d_in[2];  // (4, 336)
    float* out        = (float*)d_out;          // (224, 336)

    cudaFuncSetAttribute(gemm_mma, cudaFuncAttributeMaxDynamicSharedMemorySize,
                         SMEM_NEED);
    split_x<<<(M_ROWS * K_DIM) / (256 * 4), 256>>>(X);
    dim3 grid(2 * NT, SPLITS);      // 28 x 21 = 588 CTAs, 2/SM -> ~2 waves
    gemm_mma<<<grid, THREADS, SMEM_NEED>>>(W);
    reduce_iswt<<<M_ROWS, 352>>>(bias, out);
}

// round 8
// speedup vs baseline: 1.0903x; 1.0903x over previous
#include <cuda_runtime.h>
#include <cuda_bf16.h>
#include <cstdint>

// ---------------------------------------------------------------- constants
#define M_ROWS 224      // B*N
#define K_DIM  49152
#define PRED   336
#define NCOLS  1344

#define SPLITS    21
#define BN        96
#define NT        14    // 1344/96
#define KT        64    // k per stage
#define THREADS   448   // 14 warps: 7 (m) x 2 (n), warp tile 32x48

// smem stage layout (bytes). fp32/tf32 storage, 272B row stride (256 + 16 pad)
#define A_STRIDE 272
#define B_STRIDE 272
#define A_OFF    0
#define B_OFF    60928   // 224*272
#define STAGE    87040   // + 96*272
#define SMEM_NEED (2 * STAGE)

// scratch
__device__ float g_part[SPLITS * M_ROWS * NCOLS];
__device__ float g_XT[(size_t)M_ROWS * K_DIM];   // X rounded to tf32

// db4 reconstruction filters
__constant__ float c_RL[8] = {
     0.23037781330885523f,  0.7148465705525415f,   0.6308807679295904f,
    -0.02798376941698385f, -0.18703481171888114f,  0.030841381835986965f,
     0.032883011666982945f, -0.010597401784997278f };
__constant__ float c_RH[8] = {
     0.010597401784997278f, 0.032883011666982945f, -0.030841381835986965f,
    -0.18703481171888114f,  0.02798376941698385f,   0.6308807679295904f,
    -0.7148465705525415f,   0.23037781330885523f };

// ---------------------------------------------------------------- helpers
__device__ __forceinline__ uint32_t smem_u32(const void* p) {
    uint32_t a;
    asm("{ .reg .u64 t; cvta.to.shared.u64 t, %1; cvt.u32.u64 %0, t; }"
        : "=r"(a) : "l"(p));
    return a;
}
__device__ __forceinline__ uint32_t to_tf32(float f) {
    uint32_t r;
    asm("cvt.rna.tf32.f32 %0, %1;" : "=r"(r) : "f"(f));
    return r;
}

#define CP_ASYNC16(saddr, gptr)                                               \
    asm volatile("cp.async.cg.shared.global [%0], [%1], 16;"                  \
        :: "r"(saddr), "l"(gptr))
#define CP_COMMIT() asm volatile("cp.async.commit_group;" ::: "memory")
#define CP_WAIT0()  asm volatile("cp.async.wait_group 0;" ::: "memory")

// ldmatrix b16 x4 on tf32 data: one x4 covers a 16x8 tf32 tile (16x16 b16);
// register mapping matches m16n8k8 tf32 fragments exactly.
#define LDSM_X4(r0, r1, r2, r3, addr)                                         \
    asm volatile("ldmatrix.sync.aligned.m8n8.x4.shared.b16 {%0,%1,%2,%3},[%4];" \
        : "=r"(r0), "=r"(r1), "=r"(r2), "=r"(r3) : "r"(addr))

#define MMA_TF32(C, A0, A1, A2, A3, B0, B1)                                   \
  asm volatile(                                                               \
      "mma.sync.aligned.m16n8k8.row.col.f32.tf32.tf32.f32 "                   \
      "{%0,%1,%2,%3}, {%4,%5,%6,%7}, {%8,%9}, {%0,%1,%2,%3};\n"               \
      : "+f"(C[0]), "+f"(C[1]), "+f"(C[2]), "+f"(C[3])                        \
      : "r"(A0), "r"(A1), "r"(A2), "r"(A3), "r"(B0), "r"(B1))

// ---------------------------------------------------------------------------
// Pre-pass: round X to tf32 (RNA) once; GEMM then cp.asyncs it verbatim.
// ---------------------------------------------------------------------------
__global__ void __launch_bounds__(256) round_x(const float* __restrict__ X)
{
    const size_t i = ((size_t)blockIdx.x * 256 + threadIdx.x) * 4;
    const float4 v = *reinterpret_cast<const float4*>(X + i);
    uint4 o;
    o.x = to_tf32(v.x); o.y = to_tf32(v.y);
    o.z = to_tf32(v.z); o.w = to_tf32(v.w);
    *reinterpret_cast<uint4*>(g_XT + i) = o;
}

// ---------------------------------------------------------------------------
// GEMM: C[224,1344] = X @ Wcat (split-K partials), single-product tf32 MMA.
// A: [m][k] tf32 via cp.async. B: [n][k] tf32 (transposed store, RNA cvt).
// ---------------------------------------------------------------------------
__global__ void __launch_bounds__(THREADS, 1)
gemm_mma(const float* __restrict__ W)
{
    extern __shared__ char smem[];
    const uint32_t sb = smem_u32(smem);
    const int t    = threadIdx.x;
    const int lane = t & 31;
    const int warp = t >> 5;
    const int n0   = blockIdx.x * BN;
    const int split = blockIdx.y;
    // 768 k64-tiles over 21 splits: first 12 get 37, rest 36
    const int start = split * 36 + (split < 12 ? split : 12);
    const int count = 36 + (split < 12 ? 1 : 0);

    // ---- A producer: 3584 16B chunks (224 rows x 16 kc), 8/thread ----
    uint32_t agoff[8], asoff[8];
    #pragma unroll
    for (int i = 0; i < 8; ++i) {
        int c = t + i * THREADS;          // 0..3583
        int row = c >> 4;
        int kc  = c & 15;                 // 16B chunk within 64-float row
        agoff[i] = (uint32_t)(row * K_DIM + start * KT + kc * 4) * 4u; // bytes
        asoff[i] = A_OFF + row * A_STRIDE + kc * 16;
    }
    const char* abase = reinterpret_cast<const char*>(g_XT);

    // ---- B producer: 1536 float4 chunks (64 k x 24 n-groups), <=4/thread ----
    uint32_t bgoff[4], bsoff[4];
    bool bval[4];
    #pragma unroll
    for (int i = 0; i < 4; ++i) {
        int c = t + i * THREADS;
        bval[i] = (c < 64 * 24);
        int cc = bval[i] ? c : 0;
        int krow = cc / 24, nc = cc - krow * 24;
        int nB = n0 + nc * 4;
        int band = nB / PRED, p = nB - band * PRED;
        bgoff[i] = (uint32_t)((band * K_DIM + start * KT + krow) * PRED + p) * 4u;
        bsoff[i] = B_OFF + (nc * 4) * B_STRIDE + krow * 4;   // rows n, col k
    }
    const char* wbase = reinterpret_cast<const char*>(W);

    // ---- consumer: warp tile 32(m) x 48(n); warps 7m x 2n ----
    const int mw = warp >> 1, nw = warp & 1;
    const int mbase = mw * 32, nbase = nw * 48;
    const int li = lane & 7, lj = lane >> 3;
    int arel[2], brel[3];
    #pragma unroll
    for (int mf = 0; mf < 2; ++mf)
        arel[mf] = A_OFF + (mbase + mf * 16 + (lj & 1) * 8 + li) * A_STRIDE
                 + ((lj & 2) ? 16 : 0);
    #pragma unroll
    for (int nf = 0; nf < 3; ++nf)
        brel[nf] = B_OFF + (nbase + nf * 16 + (lj & 1) * 8 + li) * B_STRIDE
                 + ((lj & 2) ? 16 : 0);

    float acc[2][6][4];
    #pragma unroll
    for (int m = 0; m < 2; ++m)
        #pragma unroll
        for (int n = 0; n < 6; ++n)
            #pragma unroll
            for (int q = 0; q < 4; ++q) acc[m][n][q] = 0.f;

    // ---- prologue: fill stage 0 ----
    {
        #pragma unroll
        for (int i = 0; i < 8; ++i)
            CP_ASYNC16(sb + asoff[i], abase + agoff[i]);
        CP_COMMIT();
        #pragma unroll
        for (int i = 0; i < 4; ++i) {
            if (!bval[i]) continue;
            const float4 f = *reinterpret_cast<const float4*>(wbase + bgoff[i]);
            char* d = smem + bsoff[i];
            *reinterpret_cast<uint32_t*>(d)                = to_tf32(f.x);
            *reinterpret_cast<uint32_t*>(d + B_STRIDE)     = to_tf32(f.y);
            *reinterpret_cast<uint32_t*>(d + 2 * B_STRIDE) = to_tf32(f.z);
            *reinterpret_cast<uint32_t*>(d + 3 * B_STRIDE) = to_tf32(f.w);
        }
        CP_WAIT0();
        __syncthreads();
    }

    // ---- main loop (2-stage) ----
    for (int it = 0; it < count; ++it) {
        const int ss = it & 1;
        const uint32_t ab = sb + ss * STAGE;
        const bool more = (it + 1 < count);

        float4 fb[4];
        if (more) {
            const uint32_t nsb = sb + (ss ^ 1) * STAGE;
            const uint32_t ao = (uint32_t)(it + 1) * KT * 4u;    // bytes
            #pragma unroll
            for (int i = 0; i < 8; ++i)
                CP_ASYNC16(nsb + asoff[i], abase + agoff[i] + ao);
            CP_COMMIT();
            const uint32_t bo = (uint32_t)(it + 1) * KT * PRED * 4u;
            #pragma unroll
            for (int i = 0; i < 4; ++i)
                fb[i] = bval[i]
                      ? *reinterpret_cast<const float4*>(wbase + bgoff[i] + bo)
                      : make_float4(0, 0, 0, 0);
        }

        // compute on stage ss: 8 x k8
        #pragma unroll
        for (int k8 = 0; k8 < 8; ++k8) {
            uint32_t a[2][4];
            #pragma unroll
            for (int mf = 0; mf < 2; ++mf)
                LDSM_X4(a[mf][0], a[mf][1], a[mf][2], a[mf][3],
                        ab + arel[mf] + k8 * 32);
            #pragma unroll
            for (int nf = 0; nf < 3; ++nf) {
                uint32_t b0lo, b0hi, b1lo, b1hi;
                LDSM_X4(b0lo, b0hi, b1lo, b1hi, ab + brel[nf] + k8 * 32);
                #pragma unroll
                for (int mf = 0; mf < 2; ++mf) {
                    MMA_TF32(acc[mf][2*nf],   a[mf][0], a[mf][1], a[mf][2], a[mf][3], b0lo, b1lo);
                    MMA_TF32(acc[mf][2*nf+1], a[mf][0], a[mf][1], a[mf][2], a[mf][3], b0hi, b1hi);
                }
            }
        }

        if (more) {
            char* nst = smem + (ss ^ 1) * STAGE;
            #pragma unroll
            for (int i = 0; i < 4; ++i) {
                if (!bval[i]) continue;
                char* d = nst + bsoff[i];
                *reinterpret_cast<uint32_t*>(d)                = to_tf32(fb[i].x);
                *reinterpret_cast<uint32_t*>(d + B_STRIDE)     = to_tf32(fb[i].y);
                *reinterpret_cast<uint32_t*>(d + 2 * B_STRIDE) = to_tf32(fb[i].z);
                *reinterpret_cast<uint32_t*>(d + 3 * B_STRIDE) = to_tf32(fb[i].w);
            }
            CP_WAIT0();
        }
        __syncthreads();
    }

    // ---- epilogue: split-K partials ----
    float* gp = g_part + (size_t)split * M_ROWS * NCOLS;
    const int rr = lane >> 2, cc = (lane & 3) * 2;
    #pragma unroll
    for (int mf = 0; mf < 2; ++mf) {
        const int row = mbase + mf * 16 + rr;
        #pragma unroll
        for (int ns = 0; ns < 6; ++ns) {
            const int col = n0 + nbase + ns * 8 + cc;
            *reinterpret_cast<float2*>(gp + (size_t)row * NCOLS + col) =
                make_float2(acc[mf][ns][0], acc[mf][ns][1]);
            *reinterpret_cast<float2*>(gp + (size_t)(row + 8) * NCOLS + col) =
                make_float2(acc[mf][ns][2], acc[mf][ns][3]);
        }
    }
}

// ---------------------------------------------------------------------------
// Split-K reduce + bias + 3-level inverse SWT (db4, periodization)
// ---------------------------------------------------------------------------
__global__ void reduce_iswt(const float* __restrict__ bias, float* __restrict__ out)
{
    __shared__ float sc[4][PRED];
    const int t   = threadIdx.x;
    const int row = blockIdx.x;

    if (t < PRED) {
        #pragma unroll
        for (int band = 0; band < 4; ++band) {
            float a = bias[band * PRED + t];
            const float* gp = g_part + (size_t)row * NCOLS + band * PRED + t;
            #pragma unroll
            for (int s = 0; s < SPLITS; ++s)
                a += gp[(size_t)s * M_ROWS * NCOLS];
            sc[band][t] = a;
        }
    }
    __syncthreads();

    const int steps[3] = {4, 2, 1};
    #pragma unroll
    for (int lv = 0; lv < 3; ++lv) {
        const int step = steps[lv];
        const int band = lv + 1;
        const int Mlen = PRED / step;
        float nv = 0.f;
        if (t < PRED) {
            const int s = t % step;
            const int m = t / step;
            float x1 = 0.f, x2 = 0.f;
            #pragma unroll
            for (int k = 0; k < 8; ++k) {
                int q = m + 3 - k;
                if (q >= Mlen) q -= Mlen;
                if (q < 0)     q += Mlen;
                if ((q & 1) == 0) {
                    const int idx = q * step + s;
                    x1 += sc[0][idx] * c_RL[k] + sc[band][idx] * c_RH[k];
                }
                int q2 = m + 2 - k;
                if (q2 >= Mlen) q2 -= Mlen;
                if (q2 < 0)     q2 += Mlen;
                if ((q2 & 1) == 0) {
                    const int idx2 = (q2 + 1) * step + s;
                    x2 += sc[0][idx2] * c_RL[k] + sc[band][idx2] * c_RH[k];
                }
            }
            nv = 0.5f * (x1 + x2);
        }
        __syncthreads();
        if (t < PRED) sc[0][t] = nv;
        __syncthreads();
    }

    if (t < PRED) out[(size_t)row * PRED + t] = sc[0][t];
}

// ---------------------------------------------------------------------------
extern "C" void kernel_launch(void* const* d_in, const int* in_sizes, int n_in,
                              void* d_out, int out_size)
{
    const float* X    = (const float*)d_in[0];  // (224, 49152)
    const float* W    = (const float*)d_in[1];  // (4, 49152, 336)
    const float* bias = (const float*)d_in[2];  // (4, 336)
    float* out        = (float*)d_out;          // (224, 336)

    cudaFuncSetAttribute(gemm_mma, cudaFuncAttributeMaxDynamicSharedMemorySize,
                         SMEM_NEED);
    round_x<<<(M_ROWS * K_DIM) / (256 * 4), 256>>>(X);
    dim3 grid(NT, SPLITS);          // 14 x 21 = 294 CTAs
    gemm_mma<<<grid, THREADS, SMEM_NEED>>>(W);
    reduce_iswt<<<M_ROWS, 352>>>(bias, out);
}

// round 9
// speedup vs baseline: 1.1688x; 1.0720x over previous
#include <cuda_runtime.h>
#include <cuda_bf16.h>
#include <cstdint>

// ---------------------------------------------------------------- constants
#define M_ROWS 224      // B*N
#define K_DIM  49152
#define PRED   336
#define NCOLS  1344

#define SPLITS    21
#define BN        96
#define NT        14    // 1344/96
#define KT        64    // k per stage
#define THREADS   448   // 14 warps: 7 (m) x 2 (n), warp tile 32x48

// smem stage layout (bytes). tf32 storage, 272B row stride (256 + 16 pad)
#define A_STRIDE 272
#define B_STRIDE 272
#define A_OFF    0
#define B_OFF    60928   // 224*272
#define STAGE    87040   // + 96*272
#define SMEM_NEED (2 * STAGE)

// scratch
__device__ float g_part[SPLITS * M_ROWS * NCOLS];
__device__ float g_XT[(size_t)M_ROWS * K_DIM];   // X rounded to tf32

// db4 reconstruction filters
__constant__ float c_RL[8] = {
     0.23037781330885523f,  0.7148465705525415f,   0.6308807679295904f,
    -0.02798376941698385f, -0.18703481171888114f,  0.030841381835986965f,
     0.032883011666982945f, -0.010597401784997278f };
__constant__ float c_RH[8] = {
     0.010597401784997278f, 0.032883011666982945f, -0.030841381835986965f,
    -0.18703481171888114f,  0.02798376941698385f,   0.6308807679295904f,
    -0.7148465705525415f,   0.23037781330885523f };

// ---------------------------------------------------------------- helpers
__device__ __forceinline__ uint32_t smem_u32(const void* p) {
    uint32_t a;
    asm("{ .reg .u64 t; cvta.to.shared.u64 t, %1; cvt.u32.u64 %0, t; }"
        : "=r"(a) : "l"(p));
    return a;
}
__device__ __forceinline__ uint32_t to_tf32(float f) {
    uint32_t r;
    asm("cvt.rna.tf32.f32 %0, %1;" : "=r"(r) : "f"(f));
    return r;
}

#define CP_ASYNC16(saddr, gptr)                                               \
    asm volatile("cp.async.cg.shared.global [%0], [%1], 16;"                  \
        :: "r"(saddr), "l"(gptr))
#define CP_COMMIT() asm volatile("cp.async.commit_group;" ::: "memory")
#define CP_WAIT0()  asm volatile("cp.async.wait_group 0;" ::: "memory")

// ldmatrix b16 x4 on tf32 data: one x4 covers a 16x8 tf32 tile; register
// mapping matches m16n8k8 tf32 fragments exactly.
#define LDSM_X4(r0, r1, r2, r3, addr)                                         \
    asm volatile("ldmatrix.sync.aligned.m8n8.x4.shared.b16 {%0,%1,%2,%3},[%4];" \
        : "=r"(r0), "=r"(r1), "=r"(r2), "=r"(r3) : "r"(addr))

#define MMA_TF32(C, A0, A1, A2, A3, B0, B1)                                   \
  asm volatile(                                                               \
      "mma.sync.aligned.m16n8k8.row.col.f32.tf32.tf32.f32 "                   \
      "{%0,%1,%2,%3}, {%4,%5,%6,%7}, {%8,%9}, {%0,%1,%2,%3};\n"               \
      : "+f"(C[0]), "+f"(C[1]), "+f"(C[2]), "+f"(C[3])                        \
      : "r"(A0), "r"(A1), "r"(A2), "r"(A3), "r"(B0), "r"(B1))

// quad-local 4x4 transpose: lane li of each quad holds v[j] = M[li][j];
// afterwards v[c] = M[c][li].
__device__ __forceinline__ void quad_transpose(float v[4], int li) {
    float x = (li & 1) ? v[0] : v[1];
    float y = (li & 1) ? v[2] : v[3];
    x = __shfl_xor_sync(0xffffffffu, x, 1);
    y = __shfl_xor_sync(0xffffffffu, y, 1);
    if (li & 1) { v[0] = x; v[2] = y; } else { v[1] = x; v[3] = y; }
    x = (li & 2) ? v[0] : v[2];
    y = (li & 2) ? v[1] : v[3];
    x = __shfl_xor_sync(0xffffffffu, x, 2);
    y = __shfl_xor_sync(0xffffffffu, y, 2);
    if (li & 2) { v[0] = x; v[1] = y; } else { v[2] = x; v[3] = y; }
}

// ---------------------------------------------------------------------------
// Pre-pass: round X to tf32 (RNA) once; GEMM then cp.asyncs it verbatim.
// ---------------------------------------------------------------------------
__global__ void __launch_bounds__(256) round_x(const float* __restrict__ X)
{
    const size_t i = ((size_t)blockIdx.x * 256 + threadIdx.x) * 4;
    const float4 v = *reinterpret_cast<const float4*>(X + i);
    uint4 o;
    o.x = to_tf32(v.x); o.y = to_tf32(v.y);
    o.z = to_tf32(v.z); o.w = to_tf32(v.w);
    *reinterpret_cast<uint4*>(g_XT + i) = o;
}

// ---------------------------------------------------------------------------
// GEMM: C[224,1344] = X @ Wcat (split-K partials), single-product tf32 MMA.
// A: [m][k] tf32 via cp.async. B: [n][k] via shuffle-transpose + STS.128
// (conflict-free; replaces round-8's 12-way-conflicted scalar STS).
// ---------------------------------------------------------------------------
__global__ void __launch_bounds__(THREADS, 1)
gemm_mma(const float* __restrict__ W)
{
    extern __shared__ char smem[];
    const uint32_t sb = smem_u32(smem);
    const int t    = threadIdx.x;
    const int lane = t & 31;
    const int warp = t >> 5;
    const int n0   = blockIdx.x * BN;
    const int split = blockIdx.y;
    // 768 k64-tiles over 21 splits: first 12 get 37, rest 36
    const int start = split * 36 + (split < 12 ? split : 12);
    const int count = 36 + (split < 12 ? 1 : 0);

    // ---- A producer: 3584 16B chunks (224 rows x 16 kc), 8/thread ----
    uint32_t agoff[8], asoff[8];
    #pragma unroll
    for (int i = 0; i < 8; ++i) {
        int c = t + i * THREADS;          // 0..3583
        int row = c >> 4;
        int kc  = c & 15;
        agoff[i] = (uint32_t)(row * K_DIM + start * KT + kc * 4) * 4u; // bytes
        asoff[i] = A_OFF + row * A_STRIDE + kc * 16;
    }
    const char* abase = reinterpret_cast<const char*>(g_XT);

    // ---- B producer: 1536 float4 chunks; quad layout for shuffle-transpose.
    // chunk c: nc = (c>>2)%24 (4-col group), li = c&3 (k within quad),
    //          kq = c/96 (k-quad). Thread loads W[krow=kq*4+li][4nc..4nc+3];
    // after quad_transpose it owns n = nc*4+li, k = kq*4..kq*4+3 -> STS.128.
    const int bli = t & 3;
    uint32_t bgoff[4], bsoff[4];
    #pragma unroll
    for (int i = 0; i < 4; ++i) {
        int c = t + i * THREADS;
        int cc = (c < 1536) ? c : 0;      // warp-uniform validity (1536-1344=192, warp aligned)
        int nc = (cc >> 2) % 24;
        int kq = cc / 96;
        int krow = kq * 4 + bli;
        int nB = n0 + nc * 4;
        int band = nB / PRED, p = nB - band * PRED;
        bgoff[i] = (uint32_t)((band * K_DIM + start * KT + krow) * PRED + p) * 4u;
        bsoff[i] = B_OFF + (nc * 4 + bli) * B_STRIDE + kq * 16;
    }
    const char* wbase = reinterpret_cast<const char*>(W);
    const bool bv3 = (t < 192);           // chunk i=3 valid only for t<192 (warps 0-5)

    // ---- consumer: warp tile 32(m) x 48(n); warps 7m x 2n ----
    const int mw = warp >> 1, nw = warp & 1;
    const int mbase = mw * 32, nbase = nw * 48;
    const int li = lane & 7, lj = lane >> 3;
    int arel[2], brel[3];
    #pragma unroll
    for (int mf = 0; mf < 2; ++mf)
        arel[mf] = A_OFF + (mbase + mf * 16 + (lj & 1) * 8 + li) * A_STRIDE
                 + ((lj & 2) ? 16 : 0);
    #pragma unroll
    for (int nf = 0; nf < 3; ++nf)
        brel[nf] = B_OFF + (nbase + nf * 16 + (lj & 1) * 8 + li) * B_STRIDE
                 + ((lj & 2) ? 16 : 0);

    float acc[2][6][4];
    #pragma unroll
    for (int m = 0; m < 2; ++m)
        #pragma unroll
        for (int n = 0; n < 6; ++n)
            #pragma unroll
            for (int q = 0; q < 4; ++q) acc[m][n][q] = 0.f;

    // ---- prologue: fill stage 0 ----
    {
        #pragma unroll
        for (int i = 0; i < 8; ++i)
            CP_ASYNC16(sb + asoff[i], abase + agoff[i]);
        CP_COMMIT();
        #pragma unroll
        for (int i = 0; i < 4; ++i) {
            if (i == 3 && !bv3) continue;
            float4 f = *reinterpret_cast<const float4*>(wbase + bgoff[i]);
            float v[4] = { f.x, f.y, f.z, f.w };
            quad_transpose(v, bli);
            *reinterpret_cast<uint4*>(smem + bsoff[i]) =
                make_uint4(to_tf32(v[0]), to_tf32(v[1]), to_tf32(v[2]), to_tf32(v[3]));
        }
        CP_WAIT0();
        __syncthreads();
    }

    // ---- main loop (2-stage) ----
    for (int it = 0; it < count; ++it) {
        const int ss = it & 1;
        const uint32_t ab = sb + ss * STAGE;
        const bool more = (it + 1 < count);

        float4 fb[4];
        if (more) {
            const uint32_t nsb = sb + (ss ^ 1) * STAGE;
            const uint32_t ao = (uint32_t)(it + 1) * KT * 4u;    // bytes
            #pragma unroll
            for (int i = 0; i < 8; ++i)
                CP_ASYNC16(nsb + asoff[i], abase + agoff[i] + ao);
            CP_COMMIT();
            const uint32_t bo = (uint32_t)(it + 1) * KT * PRED * 4u;
            #pragma unroll
            for (int i = 0; i < 4; ++i)
                fb[i] = (i < 3 || bv3)
                      ? *reinterpret_cast<const float4*>(wbase + bgoff[i] + bo)
                      : make_float4(0, 0, 0, 0);
        }

        // compute on stage ss: 8 x k8
        #pragma unroll
        for (int k8 = 0; k8 < 8; ++k8) {
            uint32_t a[2][4];
            #pragma unroll
            for (int mf = 0; mf < 2; ++mf)
                LDSM_X4(a[mf][0], a[mf][1], a[mf][2], a[mf][3],
                        ab + arel[mf] + k8 * 32);
            #pragma unroll
            for (int nf = 0; nf < 3; ++nf) {
                uint32_t b0lo, b0hi, b1lo, b1hi;
                LDSM_X4(b0lo, b0hi, b1lo, b1hi, ab + brel[nf] + k8 * 32);
                #pragma unroll
                for (int mf = 0; mf < 2; ++mf) {
                    MMA_TF32(acc[mf][2*nf],   a[mf][0], a[mf][1], a[mf][2], a[mf][3], b0lo, b1lo);
                    MMA_TF32(acc[mf][2*nf+1], a[mf][0], a[mf][1], a[mf][2], a[mf][3], b0hi, b1hi);
                }
            }
        }

        if (more) {
            char* nst = smem + (ss ^ 1) * STAGE;
            #pragma unroll
            for (int i = 0; i < 4; ++i) {
                if (i == 3 && !bv3) continue;
                float v[4] = { fb[i].x, fb[i].y, fb[i].z, fb[i].w };
                quad_transpose(v, bli);
                *reinterpret_cast<uint4*>(nst + bsoff[i]) =
                    make_uint4(to_tf32(v[0]), to_tf32(v[1]), to_tf32(v[2]), to_tf32(v[3]));
            }
            CP_WAIT0();
        }
        __syncthreads();
    }

    // ---- epilogue: split-K partials ----
    float* gp = g_part + (size_t)split * M_ROWS * NCOLS;
    const int rr = lane >> 2, cc = (lane & 3) * 2;
    #pragma unroll
    for (int mf = 0; mf < 2; ++mf) {
        const int row = mbase + mf * 16 + rr;
        #pragma unroll
        for (int ns = 0; ns < 6; ++ns) {
            const int col = n0 + nbase + ns * 8 + cc;
            *reinterpret_cast<float2*>(gp + (size_t)row * NCOLS + col) =
                make_float2(acc[mf][ns][0], acc[mf][ns][1]);
            *reinterpret_cast<float2*>(gp + (size_t)(row + 8) * NCOLS + col) =
                make_float2(acc[mf][ns][2], acc[mf][ns][3]);
        }
    }
}

// ---------------------------------------------------------------------------
// Split-K reduce + bias + 3-level inverse SWT (db4, periodization)
// ---------------------------------------------------------------------------
__global__ void reduce_iswt(const float* __restrict__ bias, float* __restrict__ out)
{
    __shared__ float sc[4][PRED];
    const int t   = threadIdx.x;
    const int row = blockIdx.x;

    if (t < PRED) {
        #pragma unroll
        for (int band = 0; band < 4; ++band) {
            float a = bias[band * PRED + t];
            const float* gp = g_part + (size_t)row * NCOLS + band * PRED + t;
            #pragma unroll
            for (int s = 0; s < SPLITS; ++s)
                a += gp[(size_t)s * M_ROWS * NCOLS];
            sc[band][t] = a;
        }
    }
    __syncthreads();

    const int steps[3] = {4, 2, 1};
    #pragma unroll
    for (int lv = 0; lv < 3; ++lv) {
        const int step = steps[lv];
        const int band = lv + 1;
        const int Mlen = PRED / step;
        float nv = 0.f;
        if (t < PRED) {
            const int s = t % step;
            const int m = t / step;
            float x1 = 0.f, x2 = 0.f;
            #pragma unroll
            for (int k = 0; k < 8; ++k) {
                int q = m + 3 - k;
                if (q >= Mlen) q -= Mlen;
                if (q < 0)     q += Mlen;
                if ((q & 1) == 0) {
                    const int idx = q * step + s;
                    x1 += sc[0][idx] * c_RL[k] + sc[band][idx] * c_RH[k];
                }
                int q2 = m + 2 - k;
                if (q2 >= Mlen) q2 -= Mlen;
                if (q2 < 0)     q2 += Mlen;
                if ((q2 & 1) == 0) {
                    const int idx2 = (q2 + 1) * step + s;
                    x2 += sc[0][idx2] * c_RL[k] + sc[band][idx2] * c_RH[k];
                }
            }
            nv = 0.5f * (x1 + x2);
        }
        __syncthreads();
        if (t < PRED) sc[0][t] = nv;
        __syncthreads();
    }

    if (t < PRED) out[(size_t)row * PRED + t] = sc[0][t];
}

// ---------------------------------------------------------------------------
extern "C" void kernel_launch(void* const* d_in, const int* in_sizes, int n_in,
                              void* d_out, int out_size)
{
    const float* X    = (const float*)d_in[0];  // (224, 49152)
    const float* W    = (const float*)d_in[1];  // (4, 49152, 336)
    const float* bias = (const float*)d_in[2];  // (4, 336)
    float* out        = (float*)d_out;          // (224, 336)

    cudaFuncSetAttribute(gemm_mma, cudaFuncAttributeMaxDynamicSharedMemorySize,
                         SMEM_NEED);
    round_x<<<(M_ROWS * K_DIM) / (256 * 4), 256>>>(X);
    dim3 grid(NT, SPLITS);          // 14 x 21 = 294 CTAs
    gemm_mma<<<grid, THREADS, SMEM_NEED>>>(W);
    reduce_iswt<<<M_ROWS, 352>>>(bias, out);
}